// round 8
// baseline (speedup 1.0000x reference)
#include <cuda_runtime.h>

// AdaptiveFeaturePooling: 4-level ROIAlign (out=14, sr=2) + max over levels.
// Nodes: memset(out) ; build (tables + compacted worklist) ; scatter.
// Scatter: grid=(2048,4). blockIdx.y picks the channel quarter, so each active
// block performs a single gather round (no serial phase loop). Lanes are
// (channel_quarter, x_tap): the 4 x-taps of a row share a 32B sector, so each
// warp-gather touches 8 L1 lines; a 2-step shfl_xor butterfly completes the
// bilinear sum and lane 0 stores the channel result.

#define OUTSZ  14
#define CELLS  196
#define CH     256
#define GSAMP  28           // OUTSZ*2
#define MAXROI 512
#define CGRID  2048

// tab[r][l][a][j] = {w0, w1, lo(bits), hi(bits)}
__device__ float4 g_tab[MAXROI][4][2][GSAMP];
__device__ unsigned g_work[MAXROI * CELLS];   // (r<<12) | (cell<<4) | mask
__device__ int g_count;                        // starts 0, self-resets
__device__ int g_ticket;                       // starts 0, self-resets

__global__ __launch_bounds__(256)
void afp_build(const float* __restrict__ rois)
{
    __shared__ float s_w0[4][2][GSAMP];
    __shared__ float s_w1[4][2][GSAMP];

    const int r   = blockIdx.x;
    const int tid = threadIdx.x;

    // Bilinear prep, replicating reference fp32 op order exactly.
    if (tid < 4 * 2 * GSAMP) {
        int l   = tid / (2 * GSAMP);
        int rem = tid - l * (2 * GSAMP);
        int a   = rem / GSAMP;           // 0=y, 1=x
        int j   = rem - a * GSAMP;

        float p1 = rois[r * 4 + (a == 0 ? 1 : 0)];
        float p2 = rois[r * 4 + (a == 0 ? 3 : 2)];
        #pragma unroll
        for (int i = 3; i >= 0; --i) {
            if (i >= l) {
                float s = (float)(28 << i);
                p1 = __fmul_rn(p1, s);
                p2 = __fmul_rn(p2, s);
            }
        }
        float len  = fmaxf(__fadd_rn(p2, -p1), 1.0f);
        float t    = __fdiv_rn(len, 14.0f);
        float step = ((float)j + 0.5f) * 0.5f;
        float c    = __fadd_rn(p1, __fmul_rn(step, t));

        int L = 224 >> l;
        bool valid = (c >= -1.0f) && (c <= (float)L);
        c = fminf(fmaxf(c, 0.0f), (float)(L - 1));
        float lo   = floorf(c);
        float frac = __fadd_rn(c, -lo);
        int loi = (int)lo;
        int hii = loi + 1;
        if (loi >= L - 1) { loi = L - 1; hii = L - 1; frac = 0.0f; }
        float v  = valid ? 1.0f : 0.0f;
        float w0 = (1.0f - frac) * v;
        float w1 = frac * v;
        s_w0[l][a][j] = w0;
        s_w1[l][a][j] = w1;
        g_tab[r][l][a][j] = make_float4(w0, w1, __int_as_float(loi), __int_as_float(hii));
    }
    __syncthreads();

    // Compact (roi, cell, mask) entries for cells with any live level.
    if (tid < CELLS) {
        int py = tid / OUTSZ;
        int px = tid - py * OUTSZ;
        unsigned m = 0;
        #pragma unroll
        for (int l = 0; l < 4; ++l) {
            float wy = s_w0[l][0][2*py]   + s_w1[l][0][2*py]
                     + s_w0[l][0][2*py+1] + s_w1[l][0][2*py+1];
            float wx = s_w0[l][1][2*px]   + s_w1[l][1][2*px]
                     + s_w0[l][1][2*px+1] + s_w1[l][1][2*px+1];
            if (wy > 0.0f && wx > 0.0f) m |= (1u << l);
        }
        if (m) {
            int pos = atomicAdd(&g_count, 1);
            g_work[pos] = ((unsigned)r << 12) | ((unsigned)tid << 4) | m;
        }
    }
}

__global__ __launch_bounds__(256)
void afp_scatter(const float* __restrict__ f0, const float* __restrict__ f1,
                 const float* __restrict__ f2, const float* __restrict__ f3,
                 float* __restrict__ out)
{
    const int n   = g_count;
    const int tid = threadIdx.x;
    const int xi  = tid & 3;                   // x-tap lane within 4-lane group
    const int c   = (tid >> 2) + 64 * blockIdx.y;  // this group's channel
    const float* fl[4] = { f0, f1, f2, f3 };

    for (int e = blockIdx.x; e < n; e += CGRID) {
        unsigned w = g_work[e];
        int r    = (int)(w >> 12);
        int cell = (int)((w >> 4) & 0xFF);
        unsigned m = w & 0xF;
        int py = cell / OUTSZ;
        int px = cell - py * OUTSZ;
        int sy = 2 * py, sx = 2 * px;

        float best = 0.0f;
        #pragma unroll
        for (int l = 0; l < 4; ++l) {
            if (m & (1u << l)) {
                const int W = 224 >> l;
                const float* fc = fl[l] + (size_t)c * (W * W);

                float4 ty0 = g_tab[r][l][0][sy];
                float4 ty1 = g_tab[r][l][0][sy + 1];
                float4 tx0 = g_tab[r][l][1][sx];
                float4 tx1 = g_tab[r][l][1][sx + 1];

                // this lane's x-tap (weight + column)
                float wx; int x;
                if (xi == 0)      { wx = tx0.x; x = __float_as_int(tx0.z); }
                else if (xi == 1) { wx = tx0.y; x = __float_as_int(tx0.w); }
                else if (xi == 2) { wx = tx1.x; x = __float_as_int(tx1.z); }
                else              { wx = tx1.y; x = __float_as_int(tx1.w); }

                int y0 = __float_as_int(ty0.z) * W;
                int y1 = __float_as_int(ty0.w) * W;
                int y2 = __float_as_int(ty1.z) * W;
                int y3 = __float_as_int(ty1.w) * W;

                // 4 gathers per thread; warp touches 8 lines per LDG
                float v0 = fc[y0 + x];
                float v1 = fc[y1 + x];
                float v2 = fc[y2 + x];
                float v3 = fc[y3 + x];

                float acc = wx * (ty0.x * v0 + ty0.y * v1
                                + ty1.x * v2 + ty1.y * v3);
                acc += __shfl_xor_sync(0xFFFFFFFFu, acc, 1);
                acc += __shfl_xor_sync(0xFFFFFFFFu, acc, 2);

                best = fmaxf(best, acc * 0.25f);
            }
        }
        if (xi == 0)
            out[(size_t)r * (CH * CELLS) + (size_t)c * CELLS + cell] = best;
    }

    // Self-reset for the next graph replay: last block to finish zeroes state.
    if (tid == 0) {
        int t = atomicAdd(&g_ticket, 1);
        if (t == CGRID * 4 - 1) {
            g_count  = 0;
            g_ticket = 0;
        }
    }
}

extern "C" void kernel_launch(void* const* d_in, const int* in_sizes, int n_in,
                              void* d_out, int out_size)
{
    const float* f0   = (const float*)d_in[0];
    const float* f1   = (const float*)d_in[1];
    const float* f2   = (const float*)d_in[2];
    const float* f3   = (const float*)d_in[3];
    const float* rois = (const float*)d_in[4];
    int R = in_sizes[4] / 4;

    cudaMemsetAsync(d_out, 0, (size_t)out_size * sizeof(float));
    afp_build<<<R, 256>>>(rois);
    dim3 sgrid(CGRID, 4);
    afp_scatter<<<sgrid, 256>>>(f0, f1, f2, f3, (float*)d_out);
}

// round 9
// speedup vs baseline: 1.1537x; 1.1537x over previous
#include <cuda_runtime.h>

// AdaptiveFeaturePooling: 4-level ROIAlign (out=14, sr=2) + max over levels.
// 2 graph nodes:
//   1) fused fill+build: all 2048 blocks zero-fill the output (coalesced
//      float4, write-bound); blocks < R first build the bilinear tables and
//      the compacted worklist (hidden under the fill).
//   2) scatter: one worklist entry per block round; lanes = (channel_quarter,
//      x_tap) so each warp-gather touches 8 L1 lines; shfl butterfly reduces;
//      4-phase loop covers 256 channels. Counter self-resets via ticket.

#define OUTSZ  14
#define CELLS  196
#define CH     256
#define GSAMP  28           // OUTSZ*2
#define MAXROI 512
#define FGRID  2048
#define CGRID  2048

// tab[r][l][a][j] = {w0, w1, lo(bits), hi(bits)}
__device__ float4 g_tab[MAXROI][4][2][GSAMP];
__device__ unsigned g_work[MAXROI * CELLS];   // (r<<12) | (cell<<4) | mask
__device__ int g_count;                        // starts 0, self-resets
__device__ int g_ticket;                       // starts 0, self-resets

__global__ __launch_bounds__(256)
void afp_fill_build(const float* __restrict__ rois, int R,
                    float4* __restrict__ out4, int nf4)
{
    __shared__ float s_w0[4][2][GSAMP];
    __shared__ float s_w1[4][2][GSAMP];

    const int tid = threadIdx.x;
    const int r   = blockIdx.x;

    if (r < R) {
        // ---- build phase A: bilinear prep (reference fp32 op order) ----
        if (tid < 4 * 2 * GSAMP) {
            int l   = tid / (2 * GSAMP);
            int rem = tid - l * (2 * GSAMP);
            int a   = rem / GSAMP;       // 0=y, 1=x
            int j   = rem - a * GSAMP;

            float p1 = rois[r * 4 + (a == 0 ? 1 : 0)];
            float p2 = rois[r * 4 + (a == 0 ? 3 : 2)];
            #pragma unroll
            for (int i = 3; i >= 0; --i) {
                if (i >= l) {
                    float s = (float)(28 << i);
                    p1 = __fmul_rn(p1, s);
                    p2 = __fmul_rn(p2, s);
                }
            }
            float len  = fmaxf(__fadd_rn(p2, -p1), 1.0f);
            float t    = __fdiv_rn(len, 14.0f);
            float step = ((float)j + 0.5f) * 0.5f;
            float c    = __fadd_rn(p1, __fmul_rn(step, t));

            int L = 224 >> l;
            bool valid = (c >= -1.0f) && (c <= (float)L);
            c = fminf(fmaxf(c, 0.0f), (float)(L - 1));
            float lo   = floorf(c);
            float frac = __fadd_rn(c, -lo);
            int loi = (int)lo;
            int hii = loi + 1;
            if (loi >= L - 1) { loi = L - 1; hii = L - 1; frac = 0.0f; }
            float v  = valid ? 1.0f : 0.0f;
            float w0 = (1.0f - frac) * v;
            float w1 = frac * v;
            s_w0[l][a][j] = w0;
            s_w1[l][a][j] = w1;
            g_tab[r][l][a][j] = make_float4(w0, w1, __int_as_float(loi), __int_as_float(hii));
        }
        __syncthreads();

        // ---- build phase B: compact (roi, cell, mask) worklist ----
        if (tid < CELLS) {
            int py = tid / OUTSZ;
            int px = tid - py * OUTSZ;
            unsigned m = 0;
            #pragma unroll
            for (int l = 0; l < 4; ++l) {
                float wy = s_w0[l][0][2*py]   + s_w1[l][0][2*py]
                         + s_w0[l][0][2*py+1] + s_w1[l][0][2*py+1];
                float wx = s_w0[l][1][2*px]   + s_w1[l][1][2*px]
                         + s_w0[l][1][2*px+1] + s_w1[l][1][2*px+1];
                if (wy > 0.0f && wx > 0.0f) m |= (1u << l);
            }
            if (m) {
                int pos = atomicAdd(&g_count, 1);
                g_work[pos] = ((unsigned)r << 12) | ((unsigned)tid << 4) | m;
            }
        }
    }

    // ---- coalesced zero-fill of the whole output (all blocks) ----
    const float4 z = make_float4(0.f, 0.f, 0.f, 0.f);
    for (int i = blockIdx.x * 256 + tid; i < nf4; i += FGRID * 256)
        out4[i] = z;
}

__global__ __launch_bounds__(256)
void afp_scatter(const float* __restrict__ f0, const float* __restrict__ f1,
                 const float* __restrict__ f2, const float* __restrict__ f3,
                 float* __restrict__ out)
{
    const int n   = g_count;
    const int tid = threadIdx.x;
    const int xi  = tid & 3;             // x-tap lane within 4-lane group
    const int cq  = tid >> 2;            // channel quarter index 0..63
    const float* fl[4] = { f0, f1, f2, f3 };

    for (int e = blockIdx.x; e < n; e += CGRID) {
        unsigned w = g_work[e];
        int r    = (int)(w >> 12);
        int cell = (int)((w >> 4) & 0xFF);
        unsigned m = w & 0xF;
        int py = cell / OUTSZ;
        int px = cell - py * OUTSZ;
        int sy = 2 * py, sx = 2 * px;

        const size_t obase = (size_t)r * (CH * CELLS) + cell;

        #pragma unroll
        for (int p = 0; p < 4; ++p) {
            const int c = cq + 64 * p;   // this group's channel
            float best = 0.0f;

            #pragma unroll
            for (int l = 0; l < 4; ++l) {
                if (m & (1u << l)) {
                    const int W = 224 >> l;
                    const float* fc = fl[l] + (size_t)c * (W * W);

                    float4 ty0 = g_tab[r][l][0][sy];
                    float4 ty1 = g_tab[r][l][0][sy + 1];
                    float4 tx0 = g_tab[r][l][1][sx];
                    float4 tx1 = g_tab[r][l][1][sx + 1];

                    float wx; int x;
                    if (xi == 0)      { wx = tx0.x; x = __float_as_int(tx0.z); }
                    else if (xi == 1) { wx = tx0.y; x = __float_as_int(tx0.w); }
                    else if (xi == 2) { wx = tx1.x; x = __float_as_int(tx1.z); }
                    else              { wx = tx1.y; x = __float_as_int(tx1.w); }

                    int y0 = __float_as_int(ty0.z) * W;
                    int y1 = __float_as_int(ty0.w) * W;
                    int y2 = __float_as_int(ty1.z) * W;
                    int y3 = __float_as_int(ty1.w) * W;

                    float v0 = fc[y0 + x];
                    float v1 = fc[y1 + x];
                    float v2 = fc[y2 + x];
                    float v3 = fc[y3 + x];

                    float acc = wx * (ty0.x * v0 + ty0.y * v1
                                    + ty1.x * v2 + ty1.y * v3);
                    acc += __shfl_xor_sync(0xFFFFFFFFu, acc, 1);
                    acc += __shfl_xor_sync(0xFFFFFFFFu, acc, 2);

                    best = fmaxf(best, acc * 0.25f);
                }
            }
            if (xi == 0)
                out[obase + (size_t)c * CELLS] = best;
        }
    }

    // Self-reset for the next graph replay: last block to finish zeroes state.
    if (tid == 0) {
        int t = atomicAdd(&g_ticket, 1);
        if (t == CGRID - 1) {
            g_count  = 0;
            g_ticket = 0;
        }
    }
}

extern "C" void kernel_launch(void* const* d_in, const int* in_sizes, int n_in,
                              void* d_out, int out_size)
{
    const float* f0   = (const float*)d_in[0];
    const float* f1   = (const float*)d_in[1];
    const float* f2   = (const float*)d_in[2];
    const float* f3   = (const float*)d_in[3];
    const float* rois = (const float*)d_in[4];
    int R = in_sizes[4] / 4;

    afp_fill_build<<<FGRID, 256>>>(rois, R, (float4*)d_out, out_size / 4);
    afp_scatter<<<CGRID, 256>>>(f0, f1, f2, f3, (float*)d_out);
}

// round 10
// speedup vs baseline: 1.2134x; 1.0518x over previous
#include <cuda_runtime.h>

// AdaptiveFeaturePooling: 4-level ROIAlign (out=14, sr=2) + max over levels.
// SINGLE fused kernel, grid = R + 2048:
//   blocks < R   (builders): bilinear tables + valid-cell mask + worklist;
//                 release-signal g_bdone; then zero-fill own ROI slice,
//                 SKIPPING valid cells (scatter owns those -> no write race).
//   blocks >= R  (consumers): acquire-spin until all builders signaled, then
//                 gather/compute valid cells (lanes = channel_quarter x x_tap,
//                 8 L1 lines per warp-gather, shfl butterfly) and plain-store.
// Builders never wait => consumers' spin cannot deadlock at any occupancy.
// g_count/g_bdone/g_ticket self-reset via grid-wide ticket (graph-replayable).

#define OUTSZ  14
#define CELLS  196
#define CH     256
#define GSAMP  28           // OUTSZ*2
#define MAXROI 512
#define CGRID  2048
#define NF4    ((CH * CELLS) / 4)   // 12544 float4 per ROI slice
#define NGRP   (NF4 / CH)           // 49 float4 per channel

// tab[r][l][a][j] = {w0, w1, lo(bits), hi(bits)}
__device__ float4 g_tab[MAXROI][4][2][GSAMP];
__device__ unsigned g_work[MAXROI * CELLS];   // (r<<12) | (cell<<4) | mask
__device__ int g_count;                        // starts 0, self-resets
__device__ int g_bdone;                        // builders completed
__device__ int g_ticket;                       // starts 0, self-resets

__device__ __forceinline__ int ld_acquire(const int* p)
{
    int v;
    asm volatile("ld.acquire.gpu.s32 %0, [%1];" : "=r"(v) : "l"(p));
    return v;
}

__global__ __launch_bounds__(256)
void afp_fused(const float* __restrict__ f0, const float* __restrict__ f1,
               const float* __restrict__ f2, const float* __restrict__ f3,
               const float* __restrict__ rois, int R, float* __restrict__ out)
{
    const int tid = threadIdx.x;
    const int bid = blockIdx.x;

    if (bid < R) {
        // ============================ BUILDER ============================
        __shared__ float s_w0[4][2][GSAMP];
        __shared__ float s_w1[4][2][GSAMP];
        __shared__ unsigned char s_m[CELLS];
        __shared__ unsigned char s_anyv[NGRP];

        const int r = bid;

        // Phase A: bilinear prep (reference fp32 op order, exactly).
        if (tid < 4 * 2 * GSAMP) {
            int l   = tid / (2 * GSAMP);
            int rem = tid - l * (2 * GSAMP);
            int a   = rem / GSAMP;       // 0=y, 1=x
            int j   = rem - a * GSAMP;

            float p1 = rois[r * 4 + (a == 0 ? 1 : 0)];
            float p2 = rois[r * 4 + (a == 0 ? 3 : 2)];
            #pragma unroll
            for (int i = 3; i >= 0; --i) {
                if (i >= l) {
                    float s = (float)(28 << i);
                    p1 = __fmul_rn(p1, s);
                    p2 = __fmul_rn(p2, s);
                }
            }
            float len  = fmaxf(__fadd_rn(p2, -p1), 1.0f);
            float t    = __fdiv_rn(len, 14.0f);
            float step = ((float)j + 0.5f) * 0.5f;
            float c    = __fadd_rn(p1, __fmul_rn(step, t));

            int L = 224 >> l;
            bool valid = (c >= -1.0f) && (c <= (float)L);
            c = fminf(fmaxf(c, 0.0f), (float)(L - 1));
            float lo   = floorf(c);
            float frac = __fadd_rn(c, -lo);
            int loi = (int)lo;
            int hii = loi + 1;
            if (loi >= L - 1) { loi = L - 1; hii = L - 1; frac = 0.0f; }
            float v  = valid ? 1.0f : 0.0f;
            float w0 = (1.0f - frac) * v;
            float w1 = frac * v;
            s_w0[l][a][j] = w0;
            s_w1[l][a][j] = w1;
            g_tab[r][l][a][j] = make_float4(w0, w1, __int_as_float(loi), __int_as_float(hii));
        }
        __syncthreads();

        // Phase B: mask + compacted worklist.
        if (tid < CELLS) {
            int py = tid / OUTSZ;
            int px = tid - py * OUTSZ;
            unsigned m = 0;
            #pragma unroll
            for (int l = 0; l < 4; ++l) {
                float wy = s_w0[l][0][2*py]   + s_w1[l][0][2*py]
                         + s_w0[l][0][2*py+1] + s_w1[l][0][2*py+1];
                float wx = s_w0[l][1][2*px]   + s_w1[l][1][2*px]
                         + s_w0[l][1][2*px+1] + s_w1[l][1][2*px+1];
                if (wy > 0.0f && wx > 0.0f) m |= (1u << l);
            }
            s_m[tid] = (unsigned char)m;
            if (m) {
                int pos = atomicAdd(&g_count, 1);
                g_work[pos] = ((unsigned)r << 12) | ((unsigned)tid << 4) | m;
            }
        }
        __syncthreads();

        // Release-signal: tables + worklist for this ROI are visible.
        if (tid == 0) {
            __threadfence();
            atomicAdd(&g_bdone, 1);
        }

        // Per-4-cell-group "any valid" flags for the fast fill path.
        if (tid < NGRP) {
            int k = tid * 4;
            s_anyv[tid] = (unsigned char)(s_m[k] | s_m[k+1] | s_m[k+2] | s_m[k+3]);
        }
        __syncthreads();

        // Skip-fill: zero all invalid cells of this ROI's slice.
        float* obase = out + (size_t)r * (CH * CELLS);
        float4* o4 = reinterpret_cast<float4*>(obase);
        const float4 z4 = make_float4(0.f, 0.f, 0.f, 0.f);
        #pragma unroll 4
        for (int i = tid; i < NF4; i += 256) {
            int k = i % NGRP;            // float4 group within channel
            if (!s_anyv[k]) {
                o4[i] = z4;
            } else {
                int cell0 = k * 4;
                float* p = obase + i * 4;
                #pragma unroll
                for (int q = 0; q < 4; ++q)
                    if (!s_m[cell0 + q]) p[q] = 0.0f;
            }
        }
    } else {
        // ============================ CONSUMER ===========================
        // Wait until every builder has published its tables + entries.
        while (ld_acquire(&g_bdone) < R) __nanosleep(64);

        const int n  = g_count;
        const int xi = tid & 3;          // x-tap lane within 4-lane group
        const int cq = tid >> 2;         // channel quarter index 0..63
        const float* fl[4] = { f0, f1, f2, f3 };

        for (int e = bid - R; e < n; e += CGRID) {
            unsigned w = g_work[e];
            int r    = (int)(w >> 12);
            int cell = (int)((w >> 4) & 0xFF);
            unsigned m = w & 0xF;
            int py = cell / OUTSZ;
            int px = cell - py * OUTSZ;
            int sy = 2 * py, sx = 2 * px;

            const size_t obase = (size_t)r * (CH * CELLS) + cell;

            #pragma unroll
            for (int p = 0; p < 4; ++p) {
                const int c = cq + 64 * p;
                float best = 0.0f;

                #pragma unroll
                for (int l = 0; l < 4; ++l) {
                    if (m & (1u << l)) {
                        const int W = 224 >> l;
                        const float* fc = fl[l] + (size_t)c * (W * W);

                        float4 ty0 = g_tab[r][l][0][sy];
                        float4 ty1 = g_tab[r][l][0][sy + 1];
                        float4 tx0 = g_tab[r][l][1][sx];
                        float4 tx1 = g_tab[r][l][1][sx + 1];

                        float wx; int x;
                        if (xi == 0)      { wx = tx0.x; x = __float_as_int(tx0.z); }
                        else if (xi == 1) { wx = tx0.y; x = __float_as_int(tx0.w); }
                        else if (xi == 2) { wx = tx1.x; x = __float_as_int(tx1.z); }
                        else              { wx = tx1.y; x = __float_as_int(tx1.w); }

                        int y0 = __float_as_int(ty0.z) * W;
                        int y1 = __float_as_int(ty0.w) * W;
                        int y2 = __float_as_int(ty1.z) * W;
                        int y3 = __float_as_int(ty1.w) * W;

                        float v0 = fc[y0 + x];
                        float v1 = fc[y1 + x];
                        float v2 = fc[y2 + x];
                        float v3 = fc[y3 + x];

                        float acc = wx * (ty0.x * v0 + ty0.y * v1
                                        + ty1.x * v2 + ty1.y * v3);
                        acc += __shfl_xor_sync(0xFFFFFFFFu, acc, 1);
                        acc += __shfl_xor_sync(0xFFFFFFFFu, acc, 2);

                        best = fmaxf(best, acc * 0.25f);
                    }
                }
                if (xi == 0)
                    out[obase + (size_t)c * CELLS] = best;
            }
        }
    }

    // Self-reset for the next graph replay: last block zeroes all state.
    __syncthreads();
    if (tid == 0) {
        int t = atomicAdd(&g_ticket, 1);
        if (t == R + CGRID - 1) {
            g_count  = 0;
            g_bdone  = 0;
            g_ticket = 0;
        }
    }
}

extern "C" void kernel_launch(void* const* d_in, const int* in_sizes, int n_in,
                              void* d_out, int out_size)
{
    const float* f0   = (const float*)d_in[0];
    const float* f1   = (const float*)d_in[1];
    const float* f2   = (const float*)d_in[2];
    const float* f3   = (const float*)d_in[3];
    const float* rois = (const float*)d_in[4];
    int R = in_sizes[4] / 4;

    afp_fused<<<R + CGRID, 256>>>(f0, f1, f2, f3, rois, R, (float*)d_out);
}